// round 5
// baseline (speedup 1.0000x reference)
#include <cuda_runtime.h>
#include <math.h>

#define BATCH 4096
#define NIN   512
#define NREP  512
#define NOUT  640
#define RW    512
#define RB    64
#define NNZ   16384

// Scratch (static device globals — allowed)
__device__ float g_t[RW];                 // zero-init at load; re-zeroed by k4
__device__ float g_Wp[NOUT * NIN];
__device__ float g_bp[NOUT];
__device__ float g_lin[BATCH * NOUT];
__device__ uint2 g_pair[NNZ];             // (src | col<<10, bits(param)), row-sorted
__device__ int   g_row_start[NOUT + 1];

// ---------------------------------------------------------------------------
// K1: t = Qw^T @ wflat   (streams Qw once — measured at DRAM roofline)
// g_t is zero on entry (static init on call 1, k4 re-zeros for later calls).
// ---------------------------------------------------------------------------
__global__ __launch_bounds__(512) void k1_qwt(const float* __restrict__ Qw,
                                              const float* __restrict__ w) {
    __shared__ float s_w[256];
    const int tid = threadIdx.x;
    const int rowBase = blockIdx.x * 256;
    if (tid < 256) s_w[tid] = w[rowBase + tid];
    __syncthreads();

    float acc = 0.0f;
    const float* p = Qw + (size_t)rowBase * RW + tid;
#pragma unroll 8
    for (int i = 0; i < 256; i++) {
        acc += p[(size_t)i * RW] * s_w[i];
    }
    atomicAdd(&g_t[tid], acc);
}

// ---------------------------------------------------------------------------
// K2: Wp[i] = dot(Qw[i,:], t)   (second Qw stream — at roofline)
// Blocks 0..2559: GEMV.  Block 2560: CSR sort of bilinear nnz.
// Block 2561: bp = Qb (Qb^T b).  Extra blocks ride free under the 107us stream.
// ---------------------------------------------------------------------------
__global__ __launch_bounds__(256) void k2_wp(
    const float* __restrict__ Qw,
    const int* __restrict__ bsrc, const int* __restrict__ brow,
    const int* __restrict__ bcol, const float* __restrict__ bp_params,
    const float* __restrict__ Qb, const float* __restrict__ b) {
    const int tid = threadIdx.x;

    if (blockIdx.x >= 2560) {
        if (blockIdx.x == 2560) {
            // ---- CSR counting sort by output row ----
            __shared__ int c[NOUT];
            __shared__ int scan[NOUT];
            __shared__ int off[NOUT];
            for (int i = tid; i < NOUT; i += 256) c[i] = 0;
            __syncthreads();
            for (int k = tid; k < NNZ; k += 256) atomicAdd(&c[brow[k]], 1);
            __syncthreads();
            if (tid < 32) {  // warp 0: chunked inclusive warp-scan over 640
                int base = 0;
#pragma unroll
                for (int ch = 0; ch < NOUT / 32; ch++) {
                    int v = c[ch * 32 + tid];
#pragma unroll
                    for (int d = 1; d < 32; d <<= 1) {
                        int n = __shfl_up_sync(0xffffffffu, v, d);
                        if (tid >= d) v += n;
                    }
                    scan[ch * 32 + tid] = v + base;
                    base += __shfl_sync(0xffffffffu, v, 31);
                }
            }
            __syncthreads();
            for (int i = tid; i < NOUT; i += 256) {
                const int s = scan[i] - c[i];
                g_row_start[i] = s;
                off[i] = s;
            }
            if (tid == 0) g_row_start[NOUT] = NNZ;
            __syncthreads();
            for (int k = tid; k < NNZ; k += 256) {
                const int r = brow[k];
                const int pos = atomicAdd(&off[r], 1);
                g_pair[pos] = make_uint2(
                    (unsigned)bsrc[k] | ((unsigned)bcol[k] << 10),
                    __float_as_uint(bp_params[k]));
            }
        } else {
            // ---- bias: bp = Qb @ (Qb^T @ b) ----
            __shared__ float s_part[4][RB];
            __shared__ float s_s[RB];
            const int r = tid & 63;
            const int chunk = tid >> 6;
            float acc = 0.0f;
            for (int i = chunk * 160; i < chunk * 160 + 160; i++)
                acc += Qb[i * RB + r] * b[i];
            s_part[chunk][r] = acc;
            __syncthreads();
            if (tid < RB) {
                float a = s_part[0][tid] + s_part[1][tid] +
                          s_part[2][tid] + s_part[3][tid];
                s_s[tid] = a;
            }
            __syncthreads();
            for (int j = tid; j < NOUT; j += 256) {
                const float4* q4 = reinterpret_cast<const float4*>(Qb + j * RB);
                const float4* s4 = reinterpret_cast<const float4*>(s_s);
                float a = 0.0f;
#pragma unroll
                for (int u = 0; u < 16; u++) {
                    float4 q = q4[u];
                    float4 s = s4[u];
                    a += q.x * s.x + q.y * s.y + q.z * s.z + q.w * s.w;
                }
                g_bp[j] = a;
            }
        }
        return;
    }

    // ---- main GEMV blocks ----
    __shared__ float s_t[RW];
    for (int i = tid; i < RW; i += 256) s_t[i] = g_t[i];
    __syncthreads();

    const int warp = tid >> 5;
    const int lane = tid & 31;
    const int row0 = (blockIdx.x * 8 + warp) * 16;
    const float4* t4 = reinterpret_cast<const float4*>(s_t);

    for (int rr = 0; rr < 16; rr++) {
        const int row = row0 + rr;
        const float4* p4 = reinterpret_cast<const float4*>(Qw + (size_t)row * RW);
        float acc = 0.0f;
#pragma unroll
        for (int u = 0; u < 4; u++) {
            float4 q = p4[lane + 32 * u];
            float4 tt = t4[lane + 32 * u];
            acc += q.x * tt.x + q.y * tt.y + q.z * tt.z + q.w * tt.w;
        }
#pragma unroll
        for (int off = 16; off > 0; off >>= 1)
            acc += __shfl_xor_sync(0xffffffffu, acc, off);
        if (lane == 0) g_Wp[row] = acc;
    }
}

// ---------------------------------------------------------------------------
// K3: lin = x @ Wp^T + bp   (4096x512 @ 512x640)
// BM=BN=128, BK=16, 512 threads (16 warps), double-buffered smem,
// f32x2-packed FMA. grid (5,32)=160 blocks ~ 1 wave.
// Per kk per thread: 1 LDS.128(A) + 2 LDS.128(B) + 4 MOV + 16 FFMA2.
// ---------------------------------------------------------------------------
__global__ __launch_bounds__(512) void k3_gemm(const float* __restrict__ x) {
    __shared__ float As[2][16][128];
    __shared__ float Bs[2][16][128];

    const int tid = threadIdx.x;
    const int tx = tid & 15;      // cols tx*8 .. +7
    const int ty = tid >> 4;      // rows ty*4 .. +3
    const int bn0 = blockIdx.x * 128;
    const int bm0 = blockIdx.y * 128;

    // tile loaders: thread -> (m = tid&127, k-quad = tid>>7)
    const int lm = tid & 127;
    const int lk = tid >> 7;      // 0..3 -> k offsets lk*4..+3
    const float* ap = x    + (size_t)(bm0 + lm) * NIN + lk * 4;
    const float* bp = g_Wp + (size_t)(bn0 + lm) * NIN + lk * 4;

    unsigned long long acc[4][4];
#pragma unroll
    for (int i = 0; i < 4; i++)
#pragma unroll
        for (int j = 0; j < 4; j++) acc[i][j] = 0ull;

    // prologue: tile 0
    {
        float4 a4 = *reinterpret_cast<const float4*>(ap);
        float4 b4 = *reinterpret_cast<const float4*>(bp);
        As[0][lk * 4 + 0][lm] = a4.x; As[0][lk * 4 + 1][lm] = a4.y;
        As[0][lk * 4 + 2][lm] = a4.z; As[0][lk * 4 + 3][lm] = a4.w;
        Bs[0][lk * 4 + 0][lm] = b4.x; Bs[0][lk * 4 + 1][lm] = b4.y;
        Bs[0][lk * 4 + 2][lm] = b4.z; Bs[0][lk * 4 + 3][lm] = b4.w;
    }
    __syncthreads();

    for (int kt = 0; kt < 32; kt++) {
        const int buf = kt & 1;
        float4 a4n, b4n;
        if (kt < 31) {
            a4n = *reinterpret_cast<const float4*>(ap + (kt + 1) * 16);
            b4n = *reinterpret_cast<const float4*>(bp + (kt + 1) * 16);
        }
#pragma unroll
        for (int kk = 0; kk < 16; kk++) {
            float4 av = *reinterpret_cast<const float4*>(&As[buf][kk][ty * 4]);
            ulonglong2 b01 = *reinterpret_cast<const ulonglong2*>(&Bs[buf][kk][tx * 8]);
            ulonglong2 b23 = *reinterpret_cast<const ulonglong2*>(&Bs[buf][kk][tx * 8 + 4]);
            unsigned long long a2[4];
            asm("mov.b64 %0, {%1, %1};" : "=l"(a2[0]) : "f"(av.x));
            asm("mov.b64 %0, {%1, %1};" : "=l"(a2[1]) : "f"(av.y));
            asm("mov.b64 %0, {%1, %1};" : "=l"(a2[2]) : "f"(av.z));
            asm("mov.b64 %0, {%1, %1};" : "=l"(a2[3]) : "f"(av.w));
#pragma unroll
            for (int i = 0; i < 4; i++) {
                asm("fma.rn.f32x2 %0, %1, %2, %0;" : "+l"(acc[i][0]) : "l"(a2[i]), "l"(b01.x));
                asm("fma.rn.f32x2 %0, %1, %2, %0;" : "+l"(acc[i][1]) : "l"(a2[i]), "l"(b01.y));
                asm("fma.rn.f32x2 %0, %1, %2, %0;" : "+l"(acc[i][2]) : "l"(a2[i]), "l"(b23.x));
                asm("fma.rn.f32x2 %0, %1, %2, %0;" : "+l"(acc[i][3]) : "l"(a2[i]), "l"(b23.y));
            }
        }
        if (kt < 31) {
            __syncthreads();
            const int nb = (kt + 1) & 1;
            As[nb][lk * 4 + 0][lm] = a4n.x; As[nb][lk * 4 + 1][lm] = a4n.y;
            As[nb][lk * 4 + 2][lm] = a4n.z; As[nb][lk * 4 + 3][lm] = a4n.w;
            Bs[nb][lk * 4 + 0][lm] = b4n.x; Bs[nb][lk * 4 + 1][lm] = b4n.y;
            Bs[nb][lk * 4 + 2][lm] = b4n.z; Bs[nb][lk * 4 + 3][lm] = b4n.w;
            __syncthreads();
        }
    }

    // epilogue: unpack, add bias, store 2x float4 per row
    const float4 bp0 = *reinterpret_cast<const float4*>(&g_bp[bn0 + tx * 8]);
    const float4 bp1 = *reinterpret_cast<const float4*>(&g_bp[bn0 + tx * 8 + 4]);
#pragma unroll
    for (int i = 0; i < 4; i++) {
        const int row = bm0 + ty * 4 + i;
        float r[8];
        asm("mov.b64 {%0, %1}, %2;" : "=f"(r[0]), "=f"(r[1]) : "l"(acc[i][0]));
        asm("mov.b64 {%0, %1}, %2;" : "=f"(r[2]), "=f"(r[3]) : "l"(acc[i][1]));
        asm("mov.b64 {%0, %1}, %2;" : "=f"(r[4]), "=f"(r[5]) : "l"(acc[i][2]));
        asm("mov.b64 {%0, %1}, %2;" : "=f"(r[6]), "=f"(r[7]) : "l"(acc[i][3]));
        float4 v0 = make_float4(r[0] + bp0.x, r[1] + bp0.y, r[2] + bp0.z, r[3] + bp0.w);
        float4 v1 = make_float4(r[4] + bp1.x, r[5] + bp1.y, r[6] + bp1.z, r[7] + bp1.w);
        float* dst = g_lin + (size_t)row * NOUT + bn0 + tx * 8;
        *reinterpret_cast<float4*>(dst) = v0;
        *reinterpret_cast<float4*>(dst + 4) = v1;
    }
}

// ---------------------------------------------------------------------------
// K4: bilinear (CSR, atomic-free) + preact + gated nonlinearity.
// 512 threads = 16 warps; lanes = 32 batch elements; warps own output rows.
// Block 0 also re-zeros g_t for the next graph replay.
// ---------------------------------------------------------------------------
#define K4_W 33
extern __shared__ float k4_smem[];

__global__ __launch_bounds__(512) void k4_bilinear_gate(
    const int* __restrict__ gate_idx, float* __restrict__ out) {
    float* s_lin = k4_smem;                 // [640][33]
    float* s_pre = k4_smem + NOUT * K4_W;   // [640][33]

    const int tid  = threadIdx.x;
    const int warp = tid >> 5;
    const int lane = tid & 31;
    const int b0   = blockIdx.x * 32;

    if (blockIdx.x == 0 && tid < RW) g_t[tid] = 0.0f;  // reset for next replay

    // Load 32 batch rows of lin (bias already folded in by k3).
#pragma unroll
    for (int i = 0; i < 2; i++) {
        const int bb = warp + 16 * i;
        const float* src = g_lin + (size_t)(b0 + bb) * NOUT;
        for (int ch = lane; ch < NOUT; ch += 32)
            s_lin[ch * K4_W + bb] = src[ch];
    }
    __syncthreads();

    // CSR bilinear: warp w handles rows w, w+16, ...; lane = batch element.
    for (int row = warp; row < NOUT; row += 16) {
        const int ks = g_row_start[row];
        const int ke = g_row_start[row + 1];
        float acc = 0.0f;
        int k = ks;
        for (; k + 3 < ke; k += 4) {
#pragma unroll
            for (int u = 0; u < 4; u++) {
                const uint2 pr = g_pair[k + u];
                acc += __uint_as_float(pr.y) *
                       s_lin[(pr.x & 1023) * K4_W + lane] *
                       s_lin[((pr.x >> 10) & 1023) * K4_W + lane];
            }
        }
        for (; k < ke; k++) {
            const uint2 pr = g_pair[k];
            acc += __uint_as_float(pr.y) *
                   s_lin[(pr.x & 1023) * K4_W + lane] *
                   s_lin[((pr.x >> 10) & 1023) * K4_W + lane];
        }
        s_pre[row * K4_W + lane] = 0.1f * acc + s_lin[row * K4_W + lane];
    }
    __syncthreads();

    // Gated epilogue, coalesced stores.
#pragma unroll
    for (int i = 0; i < 2; i++) {
        const int bb = warp + 16 * i;
        float* dst = out + (size_t)(b0 + bb) * NREP;
        for (int j = lane; j < NREP; j += 32) {
            const int gi = gate_idx[j];
            const float g = s_pre[gi * K4_W + bb];
            const float sg = 1.0f / (1.0f + __expf(-g));
            dst[j] = sg * s_pre[j * K4_W + bb];
        }
    }
}

// ---------------------------------------------------------------------------
// Launch: 4 kernels total; sort/bias hidden inside k2's grid.
// ---------------------------------------------------------------------------
extern "C" void kernel_launch(void* const* d_in, const int* in_sizes, int n_in,
                              void* d_out, int out_size) {
    const float* x        = (const float*)d_in[0];
    const float* W_weight = (const float*)d_in[1];
    const float* b        = (const float*)d_in[2];
    const float* Qw       = (const float*)d_in[3];
    const float* Qb       = (const float*)d_in[4];
    const float* bi_p     = (const float*)d_in[5];
    const int*   bi_src   = (const int*)d_in[6];
    const int*   bi_row   = (const int*)d_in[7];
    const int*   bi_col   = (const int*)d_in[8];
    const int*   gate_idx = (const int*)d_in[9];
    float* out = (float*)d_out;

    static int smem_set = 0;
    const int k4_smem_bytes = 2 * NOUT * K4_W * sizeof(float);
    if (!smem_set) {
        cudaFuncSetAttribute(k4_bilinear_gate,
                             cudaFuncAttributeMaxDynamicSharedMemorySize,
                             k4_smem_bytes);
        smem_set = 1;
    }

    k1_qwt<<<1280, 512>>>(Qw, W_weight);
    k2_wp<<<2562, 256>>>(Qw, bi_src, bi_row, bi_col, bi_p, Qb, b);
    k3_gemm<<<dim3(NOUT / 128, BATCH / 128), 512>>>(x);
    k4_bilinear_gate<<<BATCH / 32, 512, k4_smem_bytes>>>(gate_idx, out);
}

// round 6
// speedup vs baseline: 1.1043x; 1.1043x over previous
#include <cuda_runtime.h>
#include <math.h>

#define BATCH 4096
#define NIN   512
#define NREP  512
#define NOUT  640
#define RW    512
#define RB    64
#define NNZ   16384

// Scratch (static device globals — allowed)
__device__ float g_t[RW];                 // zero-init at load; re-zeroed by k4
__device__ float g_Wp[NOUT * NIN];
__device__ float g_bp[NOUT];
__device__ float g_lin[BATCH * NOUT];
__device__ uint2 g_pair[NNZ];             // (src | col<<10, bits(param)), row-sorted
__device__ int   g_row_start[NOUT + 1];

// ---------------------------------------------------------------------------
// K1: t = Qw^T @ wflat   (streams Qw once — measured at DRAM roofline)
// ---------------------------------------------------------------------------
__global__ __launch_bounds__(512) void k1_qwt(const float* __restrict__ Qw,
                                              const float* __restrict__ w) {
    __shared__ float s_w[256];
    const int tid = threadIdx.x;
    const int rowBase = blockIdx.x * 256;
    if (tid < 256) s_w[tid] = w[rowBase + tid];
    __syncthreads();

    float acc = 0.0f;
    const float* p = Qw + (size_t)rowBase * RW + tid;
#pragma unroll 8
    for (int i = 0; i < 256; i++) {
        acc += p[(size_t)i * RW] * s_w[i];
    }
    atomicAdd(&g_t[tid], acc);
}

// ---------------------------------------------------------------------------
// K2: Wp[i] = dot(Qw[i,:], t)  (second Qw stream — at roofline)
// Blocks 0..2559: GEMV. Block 2560: CSR sort. Block 2561: bias.
// ---------------------------------------------------------------------------
__global__ __launch_bounds__(256) void k2_wp(
    const float* __restrict__ Qw,
    const int* __restrict__ bsrc, const int* __restrict__ brow,
    const int* __restrict__ bcol, const float* __restrict__ bp_params,
    const float* __restrict__ Qb, const float* __restrict__ b) {
    const int tid = threadIdx.x;

    if (blockIdx.x >= 2560) {
        if (blockIdx.x == 2560) {
            // ---- CSR counting sort by output row ----
            __shared__ int c[NOUT];
            __shared__ int scan[NOUT];
            __shared__ int off[NOUT];
            for (int i = tid; i < NOUT; i += 256) c[i] = 0;
            __syncthreads();
            for (int k = tid; k < NNZ; k += 256) atomicAdd(&c[brow[k]], 1);
            __syncthreads();
            if (tid < 32) {
                int base = 0;
#pragma unroll
                for (int ch = 0; ch < NOUT / 32; ch++) {
                    int v = c[ch * 32 + tid];
#pragma unroll
                    for (int d = 1; d < 32; d <<= 1) {
                        int n = __shfl_up_sync(0xffffffffu, v, d);
                        if (tid >= d) v += n;
                    }
                    scan[ch * 32 + tid] = v + base;
                    base += __shfl_sync(0xffffffffu, v, 31);
                }
            }
            __syncthreads();
            for (int i = tid; i < NOUT; i += 256) {
                const int s = scan[i] - c[i];
                g_row_start[i] = s;
                off[i] = s;
            }
            if (tid == 0) g_row_start[NOUT] = NNZ;
            __syncthreads();
            for (int k = tid; k < NNZ; k += 256) {
                const int r = brow[k];
                const int pos = atomicAdd(&off[r], 1);
                g_pair[pos] = make_uint2(
                    (unsigned)bsrc[k] | ((unsigned)bcol[k] << 10),
                    __float_as_uint(bp_params[k]));
            }
        } else {
            // ---- bias: bp = Qb @ (Qb^T @ b) ----
            __shared__ float s_part[4][RB];
            __shared__ float s_s[RB];
            const int r = tid & 63;
            const int chunk = tid >> 6;
            float acc = 0.0f;
            for (int i = chunk * 160; i < chunk * 160 + 160; i++)
                acc += Qb[i * RB + r] * b[i];
            s_part[chunk][r] = acc;
            __syncthreads();
            if (tid < RB) {
                s_s[tid] = s_part[0][tid] + s_part[1][tid] +
                           s_part[2][tid] + s_part[3][tid];
            }
            __syncthreads();
            for (int j = tid; j < NOUT; j += 256) {
                const float4* q4 = reinterpret_cast<const float4*>(Qb + j * RB);
                const float4* s4 = reinterpret_cast<const float4*>(s_s);
                float a = 0.0f;
#pragma unroll
                for (int u = 0; u < 16; u++) {
                    float4 q = q4[u];
                    float4 s = s4[u];
                    a += q.x * s.x + q.y * s.y + q.z * s.z + q.w * s.w;
                }
                g_bp[j] = a;
            }
        }
        return;
    }

    __shared__ float s_t[RW];
    for (int i = tid; i < RW; i += 256) s_t[i] = g_t[i];
    __syncthreads();

    const int warp = tid >> 5;
    const int lane = tid & 31;
    const int row0 = (blockIdx.x * 8 + warp) * 16;
    const float4* t4 = reinterpret_cast<const float4*>(s_t);

    for (int rr = 0; rr < 16; rr++) {
        const int row = row0 + rr;
        const float4* p4 = reinterpret_cast<const float4*>(Qw + (size_t)row * RW);
        float acc = 0.0f;
#pragma unroll
        for (int u = 0; u < 4; u++) {
            float4 q = p4[lane + 32 * u];
            float4 tt = t4[lane + 32 * u];
            acc += q.x * tt.x + q.y * tt.y + q.z * tt.z + q.w * tt.w;
        }
#pragma unroll
        for (int off = 16; off > 0; off >>= 1)
            acc += __shfl_xor_sync(0xffffffffu, acc, off);
        if (lane == 0) g_Wp[row] = acc;
    }
}

// ---------------------------------------------------------------------------
// K3: lin = x @ Wp^T + bp   (4096x512 @ 512x640)
// BM=64, BN=128, BK=16, 256 threads (8 warps), grid (5,64)=320, 3 blocks/SM.
// Conflict-free: B cols = lane*4 (LDS.128), A duplicated-pair broadcast LDS.64.
// Per kk per thread: 1 LDS.128 + 8 LDS.64 + 16 FFMA2.
// ---------------------------------------------------------------------------
__global__ __launch_bounds__(256, 3) void k3_gemm(const float* __restrict__ x) {
    __shared__ float As2[16][128];   // row r duplicated at [2r],[2r+1]
    __shared__ float Bs[16][128];

    const int tid  = threadIdx.x;
    const int warp = tid >> 5;
    const int lane = tid & 31;
    const int bn0 = blockIdx.x * 128;
    const int bm0 = blockIdx.y * 64;

    // loader mappings
    const int am = tid & 63;           // A row
    const int ak = tid >> 6;           // A k-quad (0..3)
    const float* ap = x + (size_t)(bm0 + am) * NIN + ak * 4;
    const int bn_0 = tid & 127;        // B row, first half
    const int bk_0 = tid >> 7;         // k-quad 0..1
    const float* bp0 = g_Wp + (size_t)(bn0 + bn_0) * NIN + bk_0 * 4;
    const float* bp1 = bp0 + 2 * 4;    // k-quads 2..3 (same n row)

    unsigned long long acc[8][2];
#pragma unroll
    for (int i = 0; i < 8; i++) { acc[i][0] = 0ull; acc[i][1] = 0ull; }

    // prologue: tile 0
    float4 a4 = *reinterpret_cast<const float4*>(ap);
    float4 b4a = *reinterpret_cast<const float4*>(bp0);
    float4 b4b = *reinterpret_cast<const float4*>(bp1);

    for (int kt = 0; kt < 32; kt++) {
        // store current tile
        {
            float2* d0 = reinterpret_cast<float2*>(&As2[ak * 4 + 0][am * 2]);
            float2* d1 = reinterpret_cast<float2*>(&As2[ak * 4 + 1][am * 2]);
            float2* d2 = reinterpret_cast<float2*>(&As2[ak * 4 + 2][am * 2]);
            float2* d3 = reinterpret_cast<float2*>(&As2[ak * 4 + 3][am * 2]);
            *d0 = make_float2(a4.x, a4.x);
            *d1 = make_float2(a4.y, a4.y);
            *d2 = make_float2(a4.z, a4.z);
            *d3 = make_float2(a4.w, a4.w);
            Bs[bk_0 * 4 + 0][bn_0] = b4a.x;
            Bs[bk_0 * 4 + 1][bn_0] = b4a.y;
            Bs[bk_0 * 4 + 2][bn_0] = b4a.z;
            Bs[bk_0 * 4 + 3][bn_0] = b4a.w;
            Bs[bk_0 * 4 + 8][bn_0] = b4b.x;
            Bs[bk_0 * 4 + 9][bn_0] = b4b.y;
            Bs[bk_0 * 4 + 10][bn_0] = b4b.z;
            Bs[bk_0 * 4 + 11][bn_0] = b4b.w;
        }
        __syncthreads();
        // prefetch next tile into registers
        if (kt < 31) {
            a4  = *reinterpret_cast<const float4*>(ap  + (kt + 1) * 16);
            b4a = *reinterpret_cast<const float4*>(bp0 + (kt + 1) * 16);
            b4b = *reinterpret_cast<const float4*>(bp1 + (kt + 1) * 16);
        }
#pragma unroll
        for (int kk = 0; kk < 16; kk++) {
            ulonglong2 bb =
                *reinterpret_cast<const ulonglong2*>(&Bs[kk][lane * 4]);
#pragma unroll
            for (int i = 0; i < 8; i++) {
                unsigned long long a2 = *reinterpret_cast<const unsigned long long*>(
                    &As2[kk][(warp * 8 + i) * 2]);
                asm("fma.rn.f32x2 %0, %1, %2, %0;"
                    : "+l"(acc[i][0]) : "l"(a2), "l"(bb.x));
                asm("fma.rn.f32x2 %0, %1, %2, %0;"
                    : "+l"(acc[i][1]) : "l"(a2), "l"(bb.y));
            }
        }
        __syncthreads();
    }

    // epilogue: unpack, add bias, store float4
    const float4 bv = *reinterpret_cast<const float4*>(&g_bp[bn0 + lane * 4]);
#pragma unroll
    for (int i = 0; i < 8; i++) {
        const int row = bm0 + warp * 8 + i;
        float r0, r1, r2, r3;
        asm("mov.b64 {%0, %1}, %2;" : "=f"(r0), "=f"(r1) : "l"(acc[i][0]));
        asm("mov.b64 {%0, %1}, %2;" : "=f"(r2), "=f"(r3) : "l"(acc[i][1]));
        float4 v = make_float4(r0 + bv.x, r1 + bv.y, r2 + bv.z, r3 + bv.w);
        *reinterpret_cast<float4*>(g_lin + (size_t)row * NOUT + bn0 + lane * 4) = v;
    }
}

// ---------------------------------------------------------------------------
// K4: bilinear (CSR, atomic-free) + preact + gate, f32x2 dual-batch lanes.
// 64 blocks x 512 threads; each lane carries 2 batch elements (64/block).
// s_lin2: float2[640][33] = 168,960 B (one block per SM).
// Warp owns rows {warp + 16*i}; preact kept in 40 float2 registers, written
// back over s_lin2 after a sync, then gated.
// ---------------------------------------------------------------------------
#define K4_P 33
extern __shared__ float2 k4_s2[];   // [640][33]

__global__ __launch_bounds__(512) void k4_bilinear_gate(
    const int* __restrict__ gate_idx, float* __restrict__ out) {
    const int tid  = threadIdx.x;
    const int warp = tid >> 5;
    const int lane = tid & 31;
    const int b0   = blockIdx.x * 64;

    if (blockIdx.x == 0 && tid < RW) g_t[tid] = 0.0f;  // reset for next replay

    // Load 64 batch rows: warp w handles bb = w, w+16, w+32, w+48.
#pragma unroll
    for (int i = 0; i < 4; i++) {
        const int bb = warp + 16 * i;
        const float* src = g_lin + (size_t)(b0 + bb) * NOUT;
        float* base = reinterpret_cast<float*>(k4_s2) + (bb & 1);
        const int pr = bb >> 1;
        for (int ch = lane; ch < NOUT; ch += 32)
            base[(ch * K4_P + pr) * 2] = src[ch];
    }
    __syncthreads();

    // CSR bilinear: warp w owns rows w, w+16, ..., 40 rows.
    const unsigned long long* s_u64 =
        reinterpret_cast<const unsigned long long*>(k4_s2) + lane;
    unsigned long long pre[40];
#pragma unroll 4
    for (int i = 0; i < 40; i++) {
        const int row = warp + 16 * i;
        const int ks = g_row_start[row];
        const int ke = g_row_start[row + 1];
        unsigned long long acc = 0ull;
        int k = ks;
        for (; k + 3 < ke; k += 4) {
#pragma unroll
            for (int u = 0; u < 4; u++) {
                const uint2 pr = g_pair[k + u];
                unsigned long long av = s_u64[(pr.x & 1023) * K4_P];
                unsigned long long bv = s_u64[((pr.x >> 10) & 1023) * K4_P];
                const float pf = __uint_as_float(pr.y);
                unsigned long long p2, t;
                asm("mov.b64 %0, {%1, %1};" : "=l"(p2) : "f"(pf));
                asm("mul.rn.f32x2 %0, %1, %2;" : "=l"(t) : "l"(av), "l"(bv));
                asm("fma.rn.f32x2 %0, %1, %2, %0;" : "+l"(acc) : "l"(t), "l"(p2));
            }
        }
        for (; k < ke; k++) {
            const uint2 pr = g_pair[k];
            unsigned long long av = s_u64[(pr.x & 1023) * K4_P];
            unsigned long long bv = s_u64[((pr.x >> 10) & 1023) * K4_P];
            const float pf = __uint_as_float(pr.y);
            unsigned long long p2, t;
            asm("mov.b64 %0, {%1, %1};" : "=l"(p2) : "f"(pf));
            asm("mul.rn.f32x2 %0, %1, %2;" : "=l"(t) : "l"(av), "l"(bv));
            asm("fma.rn.f32x2 %0, %1, %2, %0;" : "+l"(acc) : "l"(t), "l"(p2));
        }
        // preact = 0.1*acc + lin
        unsigned long long linv = s_u64[row * K4_P];
        unsigned long long c01;
        asm("mov.b64 %0, {%1, %1};" : "=l"(c01) : "f"(0.1f));
        unsigned long long pv;
        asm("mul.rn.f32x2 %0, %1, %2;" : "=l"(pv) : "l"(acc), "l"(c01));
        asm("add.rn.f32x2 %0, %1, %2;" : "+l"(pv) : "l"(pv), "l"(linv));
        pre[i] = pv;
    }
    __syncthreads();

    // write preacts back over s_lin2
    unsigned long long* s_w64 =
        reinterpret_cast<unsigned long long*>(k4_s2) + lane;
#pragma unroll 4
    for (int i = 0; i < 40; i++) {
        const int row = warp + 16 * i;
        s_w64[row * K4_P] = pre[i];
    }
    __syncthreads();

    // Gated epilogue: warp w handles bb = w, w+16, w+32, w+48.
    const float* s_f = reinterpret_cast<const float*>(k4_s2);
#pragma unroll
    for (int i = 0; i < 4; i++) {
        const int bb = warp + 16 * i;
        const int off = (bb >> 1) * 2 + (bb & 1);
        float* dst = out + (size_t)(b0 + bb) * NREP;
        for (int j = lane; j < NREP; j += 32) {
            const int gi = gate_idx[j];
            const float g = s_f[(gi * K4_P) * 2 + off];
            const float v = s_f[(j * K4_P) * 2 + off];
            dst[j] = v / (1.0f + __expf(-g));
        }
    }
}

// ---------------------------------------------------------------------------
// Launch
// ---------------------------------------------------------------------------
extern "C" void kernel_launch(void* const* d_in, const int* in_sizes, int n_in,
                              void* d_out, int out_size) {
    const float* x        = (const float*)d_in[0];
    const float* W_weight = (const float*)d_in[1];
    const float* b        = (const float*)d_in[2];
    const float* Qw       = (const float*)d_in[3];
    const float* Qb       = (const float*)d_in[4];
    const float* bi_p     = (const float*)d_in[5];
    const int*   bi_src   = (const int*)d_in[6];
    const int*   bi_row   = (const int*)d_in[7];
    const int*   bi_col   = (const int*)d_in[8];
    const int*   gate_idx = (const int*)d_in[9];
    float* out = (float*)d_out;

    static int smem_set = 0;
    const int k4_smem_bytes = NOUT * K4_P * sizeof(float2);  // 168,960
    if (!smem_set) {
        cudaFuncSetAttribute(k4_bilinear_gate,
                             cudaFuncAttributeMaxDynamicSharedMemorySize,
                             k4_smem_bytes);
        smem_set = 1;
    }

    k1_qwt<<<1280, 512>>>(Qw, W_weight);
    k2_wp<<<2562, 256>>>(Qw, bi_src, bi_row, bi_col, bi_p, Qb, b);
    k3_gemm<<<dim3(NOUT / 128, BATCH / 64), 256>>>(x);
    k4_bilinear_gate<<<BATCH / 64, 512, k4_smem_bytes>>>(gate_idx, out);
}

// round 7
// speedup vs baseline: 1.1885x; 1.0762x over previous
#include <cuda_runtime.h>
#include <math.h>

#define BATCH 4096
#define NIN   512
#define NREP  512
#define NOUT  640
#define RW    512
#define RB    64
#define NNZ   16384

// Scratch (static device globals — allowed)
__device__ float g_t[RW];                 // zero-init at load; re-zeroed by k4a
__device__ float g_Wp[NOUT * NIN];
__device__ float g_bp[NOUT];
__device__ float g_lin[BATCH * NOUT];
__device__ float g_pre[NOUT * BATCH];     // preact, TRANSPOSED [ch][batch]
__device__ uint2 g_pair[NNZ];             // (src | col<<10, bits(param)), row-sorted
__device__ int   g_row_start[NOUT + 1];

// ---------------------------------------------------------------------------
// K1: t = Qw^T @ wflat   (streams Qw once — measured at DRAM roofline)
// ---------------------------------------------------------------------------
__global__ __launch_bounds__(512) void k1_qwt(const float* __restrict__ Qw,
                                              const float* __restrict__ w) {
    __shared__ float s_w[256];
    const int tid = threadIdx.x;
    const int rowBase = blockIdx.x * 256;
    if (tid < 256) s_w[tid] = w[rowBase + tid];
    __syncthreads();

    float acc = 0.0f;
    const float* p = Qw + (size_t)rowBase * RW + tid;
#pragma unroll 8
    for (int i = 0; i < 256; i++) {
        acc += p[(size_t)i * RW] * s_w[i];
    }
    atomicAdd(&g_t[tid], acc);
}

// ---------------------------------------------------------------------------
// K2: Wp[i] = dot(Qw[i,:], t)  (second Qw stream — at roofline)
// Blocks 0..2559: GEMV. Block 2560: CSR sort. Block 2561: bias.
// ---------------------------------------------------------------------------
__global__ __launch_bounds__(256) void k2_wp(
    const float* __restrict__ Qw,
    const int* __restrict__ bsrc, const int* __restrict__ brow,
    const int* __restrict__ bcol, const float* __restrict__ bp_params,
    const float* __restrict__ Qb, const float* __restrict__ b) {
    const int tid = threadIdx.x;

    if (blockIdx.x >= 2560) {
        if (blockIdx.x == 2560) {
            // ---- CSR counting sort by output row ----
            __shared__ int c[NOUT];
            __shared__ int scan[NOUT];
            __shared__ int off[NOUT];
            for (int i = tid; i < NOUT; i += 256) c[i] = 0;
            __syncthreads();
            for (int k = tid; k < NNZ; k += 256) atomicAdd(&c[brow[k]], 1);
            __syncthreads();
            if (tid < 32) {
                int base = 0;
#pragma unroll
                for (int ch = 0; ch < NOUT / 32; ch++) {
                    int v = c[ch * 32 + tid];
#pragma unroll
                    for (int d = 1; d < 32; d <<= 1) {
                        int n = __shfl_up_sync(0xffffffffu, v, d);
                        if (tid >= d) v += n;
                    }
                    scan[ch * 32 + tid] = v + base;
                    base += __shfl_sync(0xffffffffu, v, 31);
                }
            }
            __syncthreads();
            for (int i = tid; i < NOUT; i += 256) {
                const int s = scan[i] - c[i];
                g_row_start[i] = s;
                off[i] = s;
            }
            if (tid == 0) g_row_start[NOUT] = NNZ;
            __syncthreads();
            for (int k = tid; k < NNZ; k += 256) {
                const int r = brow[k];
                const int pos = atomicAdd(&off[r], 1);
                g_pair[pos] = make_uint2(
                    (unsigned)bsrc[k] | ((unsigned)bcol[k] << 10),
                    __float_as_uint(bp_params[k]));
            }
        } else {
            // ---- bias: bp = Qb @ (Qb^T @ b) ----
            __shared__ float s_part[4][RB];
            __shared__ float s_s[RB];
            const int r = tid & 63;
            const int chunk = tid >> 6;
            float acc = 0.0f;
            for (int i = chunk * 160; i < chunk * 160 + 160; i++)
                acc += Qb[i * RB + r] * b[i];
            s_part[chunk][r] = acc;
            __syncthreads();
            if (tid < RB) {
                s_s[tid] = s_part[0][tid] + s_part[1][tid] +
                           s_part[2][tid] + s_part[3][tid];
            }
            __syncthreads();
            for (int j = tid; j < NOUT; j += 256) {
                const float4* q4 = reinterpret_cast<const float4*>(Qb + j * RB);
                const float4* s4 = reinterpret_cast<const float4*>(s_s);
                float a = 0.0f;
#pragma unroll
                for (int u = 0; u < 16; u++) {
                    float4 q = q4[u];
                    float4 s = s4[u];
                    a += q.x * s.x + q.y * s.y + q.z * s.z + q.w * s.w;
                }
                g_bp[j] = a;
            }
        }
        return;
    }

    __shared__ float s_t[RW];
    for (int i = tid; i < RW; i += 256) s_t[i] = g_t[i];
    __syncthreads();

    const int warp = tid >> 5;
    const int lane = tid & 31;
    const int row0 = (blockIdx.x * 8 + warp) * 16;
    const float4* t4 = reinterpret_cast<const float4*>(s_t);

    for (int rr = 0; rr < 16; rr++) {
        const int row = row0 + rr;
        const float4* p4 = reinterpret_cast<const float4*>(Qw + (size_t)row * RW);
        float acc = 0.0f;
#pragma unroll
        for (int u = 0; u < 4; u++) {
            float4 q = p4[lane + 32 * u];
            float4 tt = t4[lane + 32 * u];
            acc += q.x * tt.x + q.y * tt.y + q.z * tt.z + q.w * tt.w;
        }
#pragma unroll
        for (int off = 16; off > 0; off >>= 1)
            acc += __shfl_xor_sync(0xffffffffu, acc, off);
        if (lane == 0) g_Wp[row] = acc;
    }
}

// ---------------------------------------------------------------------------
// K3: lin = x @ Wp^T + bp   (4096x512 @ 512x640)
// BM=64, BN=128, BK=16, 256 threads (8 warps), grid (5,64)=320, 3 blocks/SM.
// ---------------------------------------------------------------------------
__global__ __launch_bounds__(256, 3) void k3_gemm(const float* __restrict__ x) {
    __shared__ float As2[16][128];   // row r duplicated at [2r],[2r+1]
    __shared__ float Bs[16][128];

    const int tid  = threadIdx.x;
    const int warp = tid >> 5;
    const int lane = tid & 31;
    const int bn0 = blockIdx.x * 128;
    const int bm0 = blockIdx.y * 64;

    const int am = tid & 63;
    const int ak = tid >> 6;
    const float* ap = x + (size_t)(bm0 + am) * NIN + ak * 4;
    const int bn_0 = tid & 127;
    const int bk_0 = tid >> 7;
    const float* bp0 = g_Wp + (size_t)(bn0 + bn_0) * NIN + bk_0 * 4;
    const float* bp1 = bp0 + 2 * 4;

    unsigned long long acc[8][2];
#pragma unroll
    for (int i = 0; i < 8; i++) { acc[i][0] = 0ull; acc[i][1] = 0ull; }

    float4 a4 = *reinterpret_cast<const float4*>(ap);
    float4 b4a = *reinterpret_cast<const float4*>(bp0);
    float4 b4b = *reinterpret_cast<const float4*>(bp1);

    for (int kt = 0; kt < 32; kt++) {
        {
            float2* d0 = reinterpret_cast<float2*>(&As2[ak * 4 + 0][am * 2]);
            float2* d1 = reinterpret_cast<float2*>(&As2[ak * 4 + 1][am * 2]);
            float2* d2 = reinterpret_cast<float2*>(&As2[ak * 4 + 2][am * 2]);
            float2* d3 = reinterpret_cast<float2*>(&As2[ak * 4 + 3][am * 2]);
            *d0 = make_float2(a4.x, a4.x);
            *d1 = make_float2(a4.y, a4.y);
            *d2 = make_float2(a4.z, a4.z);
            *d3 = make_float2(a4.w, a4.w);
            Bs[bk_0 * 4 + 0][bn_0] = b4a.x;
            Bs[bk_0 * 4 + 1][bn_0] = b4a.y;
            Bs[bk_0 * 4 + 2][bn_0] = b4a.z;
            Bs[bk_0 * 4 + 3][bn_0] = b4a.w;
            Bs[bk_0 * 4 + 8][bn_0] = b4b.x;
            Bs[bk_0 * 4 + 9][bn_0] = b4b.y;
            Bs[bk_0 * 4 + 10][bn_0] = b4b.z;
            Bs[bk_0 * 4 + 11][bn_0] = b4b.w;
        }
        __syncthreads();
        if (kt < 31) {
            a4  = *reinterpret_cast<const float4*>(ap  + (kt + 1) * 16);
            b4a = *reinterpret_cast<const float4*>(bp0 + (kt + 1) * 16);
            b4b = *reinterpret_cast<const float4*>(bp1 + (kt + 1) * 16);
        }
#pragma unroll
        for (int kk = 0; kk < 16; kk++) {
            ulonglong2 bb =
                *reinterpret_cast<const ulonglong2*>(&Bs[kk][lane * 4]);
#pragma unroll
            for (int i = 0; i < 8; i++) {
                unsigned long long a2 = *reinterpret_cast<const unsigned long long*>(
                    &As2[kk][(warp * 8 + i) * 2]);
                asm("fma.rn.f32x2 %0, %1, %2, %0;"
                    : "+l"(acc[i][0]) : "l"(a2), "l"(bb.x));
                asm("fma.rn.f32x2 %0, %1, %2, %0;"
                    : "+l"(acc[i][1]) : "l"(a2), "l"(bb.y));
            }
        }
        __syncthreads();
    }

    const float4 bv = *reinterpret_cast<const float4*>(&g_bp[bn0 + lane * 4]);
#pragma unroll
    for (int i = 0; i < 8; i++) {
        const int row = bm0 + warp * 8 + i;
        float r0, r1, r2, r3;
        asm("mov.b64 {%0, %1}, %2;" : "=f"(r0), "=f"(r1) : "l"(acc[i][0]));
        asm("mov.b64 {%0, %1}, %2;" : "=f"(r2), "=f"(r3) : "l"(acc[i][1]));
        float4 v = make_float4(r0 + bv.x, r1 + bv.y, r2 + bv.z, r3 + bv.w);
        *reinterpret_cast<float4*>(g_lin + (size_t)row * NOUT + bn0 + lane * 4) = v;
    }
}

// ---------------------------------------------------------------------------
// K4a: bilinear CSR -> preact, f32x2 dual-batch lanes, row-split x2.
// 128 blocks x 512 threads. Block = (batch group of 64, row half of 320).
// Preact written straight to transposed global g_pre[ch][batch] (STG.64,
// coalesced) — no register arrays, no spills, no writeback sync.
// ---------------------------------------------------------------------------
#define K4_P 33
extern __shared__ float2 k4_s2[];   // [640][33]

__global__ __launch_bounds__(512) void k4a_bilinear(void) {
    const int tid  = threadIdx.x;
    const int warp = tid >> 5;
    const int lane = tid & 31;
    const int grp  = blockIdx.x >> 1;
    const int half = blockIdx.x & 1;
    const int b0   = grp * 64;

    if (blockIdx.x == 0 && tid < RW) g_t[tid] = 0.0f;  // reset for next replay

    // Load 64 batch rows of lin into f32x2-packed smem.
#pragma unroll
    for (int i = 0; i < 4; i++) {
        const int bb = warp + 16 * i;
        const float* src = g_lin + (size_t)(b0 + bb) * NOUT;
        float* base = reinterpret_cast<float*>(k4_s2) + (bb & 1);
        const int pr = bb >> 1;
        for (int ch = lane; ch < NOUT; ch += 32)
            base[(ch * K4_P + pr) * 2] = src[ch];
    }
    __syncthreads();

    const unsigned long long* s_u64 =
        reinterpret_cast<const unsigned long long*>(k4_s2) + lane;
    unsigned long long c01;
    asm("mov.b64 %0, {%1, %1};" : "=l"(c01) : "f"(0.1f));

    // Warp owns rows half*320 + warp + 16*i, i in [0,20).
#pragma unroll 2
    for (int i = 0; i < 20; i++) {
        const int row = half * 320 + warp + 16 * i;
        const int ks = g_row_start[row];
        const int ke = g_row_start[row + 1];
        unsigned long long acc = 0ull;
        int k = ks;
        for (; k + 3 < ke; k += 4) {
#pragma unroll
            for (int u = 0; u < 4; u++) {
                const uint2 pr = g_pair[k + u];
                unsigned long long av = s_u64[(pr.x & 1023) * K4_P];
                unsigned long long bv = s_u64[((pr.x >> 10) & 1023) * K4_P];
                const float pf = __uint_as_float(pr.y);
                unsigned long long p2, t;
                asm("mov.b64 %0, {%1, %1};" : "=l"(p2) : "f"(pf));
                asm("mul.rn.f32x2 %0, %1, %2;" : "=l"(t) : "l"(av), "l"(bv));
                asm("fma.rn.f32x2 %0, %1, %2, %0;" : "+l"(acc) : "l"(t), "l"(p2));
            }
        }
        for (; k < ke; k++) {
            const uint2 pr = g_pair[k];
            unsigned long long av = s_u64[(pr.x & 1023) * K4_P];
            unsigned long long bv = s_u64[((pr.x >> 10) & 1023) * K4_P];
            const float pf = __uint_as_float(pr.y);
            unsigned long long p2, t;
            asm("mov.b64 %0, {%1, %1};" : "=l"(p2) : "f"(pf));
            asm("mul.rn.f32x2 %0, %1, %2;" : "=l"(t) : "l"(av), "l"(bv));
            asm("fma.rn.f32x2 %0, %1, %2, %0;" : "+l"(acc) : "l"(t), "l"(p2));
        }
        // preact = 0.1*acc + lin; store to transposed g_pre
        unsigned long long linv = s_u64[row * K4_P];
        unsigned long long pv;
        asm("mul.rn.f32x2 %0, %1, %2;" : "=l"(pv) : "l"(acc), "l"(c01));
        asm("add.rn.f32x2 %0, %1, %2;" : "+l"(pv) : "l"(pv), "l"(linv));
        *reinterpret_cast<unsigned long long*>(
            g_pre + (size_t)row * BATCH + b0 + 2 * lane) = pv;
    }
}

// ---------------------------------------------------------------------------
// K4b: gated nonlinearity from transposed preact.
// Block = 256 threads, tile = 32 j x 256 b. All g_pre reads coalesced along b;
// out writes are 128B-contiguous per thread (full lines).
// ---------------------------------------------------------------------------
__global__ __launch_bounds__(256) void k4b_gate(
    const int* __restrict__ gate_idx, float* __restrict__ out) {
    __shared__ float s_t[32][257];
    const int tid = threadIdx.x;
    const int b0 = blockIdx.x * 256;
    const int j0 = blockIdx.y * 32;

#pragma unroll 4
    for (int jj = 0; jj < 32; jj++) {
        const int j = j0 + jj;
        const int gi = gate_idx[j];
        const float v = g_pre[(size_t)j * BATCH + b0 + tid];
        const float g = g_pre[(size_t)gi * BATCH + b0 + tid];
        s_t[jj][tid] = v / (1.0f + __expf(-g));
    }
    __syncthreads();

    // transpose out: thread tid -> batch b0+tid, writes 32 consecutive j.
    float* dst = out + (size_t)(b0 + tid) * NREP + j0;
#pragma unroll
    for (int q = 0; q < 8; q++) {
        float4 v = make_float4(s_t[q * 4 + 0][tid], s_t[q * 4 + 1][tid],
                               s_t[q * 4 + 2][tid], s_t[q * 4 + 3][tid]);
        *reinterpret_cast<float4*>(dst + q * 4) = v;
    }
}

// ---------------------------------------------------------------------------
// Launch
// ---------------------------------------------------------------------------
extern "C" void kernel_launch(void* const* d_in, const int* in_sizes, int n_in,
                              void* d_out, int out_size) {
    const float* x        = (const float*)d_in[0];
    const float* W_weight = (const float*)d_in[1];
    const float* b        = (const float*)d_in[2];
    const float* Qw       = (const float*)d_in[3];
    const float* Qb       = (const float*)d_in[4];
    const float* bi_p     = (const float*)d_in[5];
    const int*   bi_src   = (const int*)d_in[6];
    const int*   bi_row   = (const int*)d_in[7];
    const int*   bi_col   = (const int*)d_in[8];
    const int*   gate_idx = (const int*)d_in[9];
    float* out = (float*)d_out;

    static int smem_set = 0;
    const int k4_smem_bytes = NOUT * K4_P * sizeof(float2);  // 168,960
    if (!smem_set) {
        cudaFuncSetAttribute(k4a_bilinear,
                             cudaFuncAttributeMaxDynamicSharedMemorySize,
                             k4_smem_bytes);
        smem_set = 1;
    }

    k1_qwt<<<1280, 512>>>(Qw, W_weight);
    k2_wp<<<2562, 256>>>(Qw, bi_src, bi_row, bi_col, bi_p, Qb, b);
    k3_gemm<<<dim3(NOUT / 128, BATCH / 64), 256>>>(x);
    k4a_bilinear<<<128, 512, k4_smem_bytes>>>();
    k4b_gate<<<dim3(BATCH / 256, NREP / 32), 256>>>(gate_idx, out);
}